// round 10
// baseline (speedup 1.0000x reference)
#include <cuda_runtime.h>
#include <cuda_fp16.h>
#include <cstdint>

// FlashAttention B=2,H=16,N=4096,D=64 fp32. logits=(q.k)/64.
// HMMA mma.sync path (plain-sm_103 toolchain: no tcgen05).
// R9 = R7's p-fused low-register kernel (3 CTAs/SM, 12 warps) with the ring
// FIXED: prefetch distance 1 issued at loop top, so the empty-wait targets the
// slot freed two tiles ago (1 tile of slack) instead of the just-freed slot.

namespace {
constexpr int BHn = 32;
constexpr int NSEQ = 4096;
constexpr int DH = 64;
constexpr int BM = 128;
constexpr int BN = 64;
constexpr int NKV = NSEQ / BN;  // 64
constexpr int NTH = 128;        // 4 warps
constexpr int LDS = 72;         // smem row stride (halves)
constexpr int NBUF = 3;
constexpr float QS2 = 1.4426950408889634f / 64.0f;  // log2(e)/64
constexpr size_t ELEMS = (size_t)BHn * NSEQ * DH;

__device__ __half g_kh[ELEMS];
__device__ __half g_vh[ELEMS];

// smem layout (halves): Q | buf0(K|V) | buf1 | buf2
constexpr int OQ = 0;
constexpr int QH = BM * LDS;       // 9216 halves
constexpr int KVH = 2 * BN * LDS;  // 9216 halves per buffer
constexpr int SMEM_BYTES = (QH + NBUF * KVH) * 2;  // 73728 B

__device__ __forceinline__ uint32_t s2u(const void* p) {
  return (uint32_t)__cvta_generic_to_shared(p);
}
__device__ __forceinline__ void cpa16(uint32_t dst, const void* src) {
  asm volatile("cp.async.cg.shared.global [%0], [%1], 16;" :: "r"(dst), "l"(src));
}
__device__ __forceinline__ void mbar_init(uint32_t a, uint32_t c) {
  asm volatile("mbarrier.init.shared.b64 [%0], %1;" :: "r"(a), "r"(c) : "memory");
}
__device__ __forceinline__ void mbar_arrive(uint32_t a) {
  asm volatile("mbarrier.arrive.shared.b64 _, [%0];" :: "r"(a) : "memory");
}
__device__ __forceinline__ void cpa_arrive(uint32_t a) {
  asm volatile("cp.async.mbarrier.arrive.noinc.shared.b64 [%0];" :: "r"(a) : "memory");
}
__device__ __forceinline__ void mbar_wait(uint32_t a, uint32_t ph) {
  asm volatile(
      "{\n\t.reg .pred P;\n"
      "W%=:\n\t"
      "mbarrier.try_wait.parity.acquire.cta.shared::cta.b64 P, [%0], %1, 0x989680;\n\t"
      "@P bra D%=;\n\t"
      "bra W%=;\n"
      "D%=:\n\t}"
      :: "r"(a), "r"(ph) : "memory");
}
__device__ __forceinline__ void ldsm4(uint32_t* r, uint32_t a) {
  asm volatile("ldmatrix.sync.aligned.m8n8.x4.shared.b16 {%0,%1,%2,%3}, [%4];"
               : "=r"(r[0]), "=r"(r[1]), "=r"(r[2]), "=r"(r[3]) : "r"(a));
}
__device__ __forceinline__ void ldsm4t(uint32_t* r, uint32_t a) {
  asm volatile("ldmatrix.sync.aligned.m8n8.x4.trans.shared.b16 {%0,%1,%2,%3}, [%4];"
               : "=r"(r[0]), "=r"(r[1]), "=r"(r[2]), "=r"(r[3]) : "r"(a));
}
__device__ __forceinline__ void mma16816(float* c, const uint32_t* a, const uint32_t* b) {
  asm volatile(
      "mma.sync.aligned.m16n8k16.row.col.f32.f16.f16.f32 "
      "{%0,%1,%2,%3}, {%4,%5,%6,%7}, {%8,%9}, {%0,%1,%2,%3};"
      : "+f"(c[0]), "+f"(c[1]), "+f"(c[2]), "+f"(c[3])
      : "r"(a[0]), "r"(a[1]), "r"(a[2]), "r"(a[3]), "r"(b[0]), "r"(b[1]));
}
__device__ __forceinline__ uint32_t pack2(float x, float y) {
  __half2 h = __floats2half2_rn(x, y);
  return *reinterpret_cast<uint32_t*>(&h);
}
__device__ __forceinline__ uint32_t ex2h2(uint32_t x) {
  uint32_t y;
  asm("ex2.approx.f16x2 %0, %1;" : "=r"(y) : "r"(x));
  return y;
}
__device__ __forceinline__ __half2 u2h2(uint32_t x) {
  return *reinterpret_cast<__half2*>(&x);
}
}  // namespace

// -------- prep: K,V fp32 -> fp16 ---------------------------------------------
__global__ void prep_kernel(const float* __restrict__ k, const float* __restrict__ v) {
  size_t i = (size_t)blockIdx.x * blockDim.x + threadIdx.x;
  const float4 fk = reinterpret_cast<const float4*>(k)[i];
  const float4 fv = reinterpret_cast<const float4*>(v)[i];
  reinterpret_cast<uint2*>(g_kh)[i] = make_uint2(pack2(fk.x, fk.y), pack2(fk.z, fk.w));
  reinterpret_cast<uint2*>(g_vh)[i] = make_uint2(pack2(fv.x, fv.y), pack2(fv.z, fv.w));
}

// -------- main attention kernel ----------------------------------------------
__global__ __launch_bounds__(NTH, 3)
void fa_hmma_kernel(const float* __restrict__ qg, float* __restrict__ out) {
  extern __shared__ __half sm[];
  __shared__ uint64_t barsto[2 * NBUF];  // full[0..2], empty[0..2]
  const uint32_t sb = s2u(sm);
  const uint32_t bfull = s2u(&barsto[0]);
  const uint32_t bempty = s2u(&barsto[NBUF]);

  const int tid = threadIdx.x;
  const int lane = tid & 31, warp = tid >> 5;
  const int mi = lane >> 3;
  const int li = lane & 7;
  const int bh = blockIdx.y, mblk = blockIdx.x;

  const float* qsrc = qg + ((size_t)bh * NSEQ + (size_t)mblk * BM) * DH;
  const __half* ksrc = g_kh + (size_t)bh * NSEQ * DH;
  const __half* vsrc = g_vh + (size_t)bh * NSEQ * DH;

  if (tid == 0) {
#pragma unroll
    for (int i = 0; i < NBUF; i++) {
      mbar_init(bfull + 8 * i, NTH);
      mbar_init(bempty + 8 * i, NTH);
    }
  }
  __syncthreads();

  // ---- prologue: start KV tile 0 (cp.async); convert Q meanwhile ----
  {
    const int ob = QH;  // slot 0
#pragma unroll
    for (int i = 0; i < 4; i++) {
      int idx = i * NTH + tid;
      int r = idx >> 3, c = (idx & 7) << 3;
      cpa16(sb + (uint32_t)(ob + r * LDS + c) * 2, ksrc + r * DH + c);
      cpa16(sb + (uint32_t)(ob + BN * LDS + r * LDS + c) * 2, vsrc + r * DH + c);
    }
    cpa_arrive(bfull + 0);
  }
  // Q: fp32 LDG -> scale(log2 domain) -> fp16 STS
#pragma unroll
  for (int i = 0; i < 16; i++) {
    int idx = i * NTH + tid;
    int r = idx >> 4, c = (idx & 15) << 2;
    float4 f = *reinterpret_cast<const float4*>(qsrc + r * DH + c);
    *reinterpret_cast<uint2*>(&sm[OQ + r * LDS + c]) =
        make_uint2(pack2(f.x * QS2, f.y * QS2), pack2(f.z * QS2, f.w * QS2));
  }
  __syncthreads();  // Q visible

  // ---- Q A-fragments (warp-M = 32) ----
  uint32_t qa[2][4][4];
#pragma unroll
  for (int s = 0; s < 2; s++)
#pragma unroll
    for (int kt = 0; kt < 4; kt++) {
      int row = warp * 32 + s * 16 + (mi & 1) * 8 + li;
      int col = kt * 16 + (mi >> 1) * 8;
      ldsm4(qa[s][kt], s2u(&sm[OQ + row * LDS + col]));
    }

  float oacc[2][8][4];
#pragma unroll
  for (int s = 0; s < 2; s++)
#pragma unroll
    for (int i = 0; i < 8; i++)
#pragma unroll
      for (int j = 0; j < 4; j++) oacc[s][i][j] = 0.f;
  float lsum[2][2] = {{0.f, 0.f}, {0.f, 0.f}};

#pragma unroll 1
  for (int t = 0; t < NKV; t++) {
    const int buf = t % 3;
    const int kb = QH + buf * KVH;
    const int vb = kb + BN * LDS;

    // ---- prefetch tile t+1 (distance 1, loop top: slack = 1 full tile) ----
    const int u = t + 1;
    if (u < NKV) {
      const int pb = u % 3;
      if (u >= 3) mbar_wait(bempty + 8 * pb, (uint32_t)(((u - 3) / 3) & 1));
      const __half* kn = ksrc + (size_t)u * BN * DH;
      const __half* vn = vsrc + (size_t)u * BN * DH;
      const int ob = QH + pb * KVH;
#pragma unroll
      for (int i = 0; i < 4; i++) {
        int idx = i * NTH + tid;
        int r = idx >> 3, c = (idx & 7) << 3;
        cpa16(sb + (uint32_t)(ob + r * LDS + c) * 2, kn + r * DH + c);
        cpa16(sb + (uint32_t)(ob + BN * LDS + r * LDS + c) * 2, vn + r * DH + c);
      }
      cpa_arrive(bfull + 8 * pb);
    }

    mbar_wait(bfull + 8 * buf, (uint32_t)((t / 3) & 1));

    __half2 a00 = __float2half2_rn(0.f), a01 = a00, a10 = a00, a11 = a00;

    // ---- fused per-p-block: S(p) -> exp(p) -> PV(p) ----
#pragma unroll
    for (int p = 0; p < 4; p++) {
      // S-GEMM for column group p (both M-slices, shared K fragments)
      float sc[2][2][4];
#pragma unroll
      for (int s = 0; s < 2; s++)
#pragma unroll
        for (int i = 0; i < 2; i++)
#pragma unroll
          for (int j = 0; j < 4; j++) sc[s][i][j] = 0.f;
#pragma unroll
      for (int kt = 0; kt < 4; kt++) {
        int row = p * 16 + (mi >> 1) * 8 + li;
        int col = kt * 16 + (mi & 1) * 8;
        uint32_t bf[4];
        ldsm4(bf, s2u(&sm[kb + row * LDS + col]));
#pragma unroll
        for (int s = 0; s < 2; s++) {
          mma16816(sc[s][0], qa[s][kt], bf);
          mma16816(sc[s][1], qa[s][kt], bf + 2);
        }
      }

      // exp(p): 8 f16x2 exps, pa consumed immediately by PV(p)
      uint32_t pa[2][4];
#pragma unroll
      for (int s = 0; s < 2; s++) {
        pa[s][0] = ex2h2(pack2(sc[s][0][0], sc[s][0][1]));
        pa[s][1] = ex2h2(pack2(sc[s][0][2], sc[s][0][3]));
        pa[s][2] = ex2h2(pack2(sc[s][1][0], sc[s][1][1]));
        pa[s][3] = ex2h2(pack2(sc[s][1][2], sc[s][1][3]));
      }
      a00 = __hadd2(a00, __hadd2(u2h2(pa[0][0]), u2h2(pa[0][2])));
      a01 = __hadd2(a01, __hadd2(u2h2(pa[0][1]), u2h2(pa[0][3])));
      a10 = __hadd2(a10, __hadd2(u2h2(pa[1][0]), u2h2(pa[1][2])));
      a11 = __hadd2(a11, __hadd2(u2h2(pa[1][1]), u2h2(pa[1][3])));

      // PV(p): O += P[:, p-group] @ V[p-group, :]  (V frags shared by slices)
#pragma unroll
      for (int d = 0; d < 4; d++) {
        int row = p * 16 + (mi & 1) * 8 + li;
        int col = (2 * d + (mi >> 1)) * 8;
        uint32_t bf[4];
        ldsm4t(bf, s2u(&sm[vb + row * LDS + col]));
#pragma unroll
        for (int s = 0; s < 2; s++) {
          mma16816(oacc[s][2 * d], pa[s], bf);
          mma16816(oacc[s][2 * d + 1], pa[s], bf + 2);
        }
      }
    }

    mbar_arrive(bempty + 8 * buf);  // done reading buf (K and V)

    lsum[0][0] += __low2float(a00) + __high2float(a00);
    lsum[0][1] += __low2float(a01) + __high2float(a01);
    lsum[1][0] += __low2float(a10) + __high2float(a10);
    lsum[1][1] += __low2float(a11) + __high2float(a11);
  }

  // ---- epilogue: O / max(l, eps) ----
#pragma unroll
  for (int s = 0; s < 2; s++)
#pragma unroll
    for (int h = 0; h < 2; h++) {
      float ls = lsum[s][h];
      ls += __shfl_xor_sync(0xffffffffu, ls, 1);
      ls += __shfl_xor_sync(0xffffffffu, ls, 2);
      float inv = 1.0f / fmaxf(ls, 1e-6f);
      int row = mblk * BM + warp * 32 + s * 16 + h * 8 + (lane >> 2);
      float* op = out + ((size_t)bh * NSEQ + row) * DH;
      int cb = (lane & 3) * 2;
#pragma unroll
      for (int nt = 0; nt < 8; nt++) {
        float2 f = make_float2(oacc[s][nt][2 * h] * inv, oacc[s][nt][2 * h + 1] * inv);
        *reinterpret_cast<float2*>(op + nt * 8 + cb) = f;
      }
    }
}

extern "C" void kernel_launch(void* const* d_in, const int* in_sizes, int n_in,
                              void* d_out, int out_size) {
  const float* q = (const float*)d_in[0];
  const float* k = (const float*)d_in[1];
  const float* v = (const float*)d_in[2];
  float* out = (float*)d_out;

  prep_kernel<<<(int)(ELEMS / 4 / 256), 256>>>(k, v);

  cudaFuncSetAttribute(fa_hmma_kernel, cudaFuncAttributeMaxDynamicSharedMemorySize,
                       SMEM_BYTES);
  dim3 grid(NSEQ / BM, BHn);
  fa_hmma_kernel<<<grid, NTH, SMEM_BYTES>>>(q, out);
}

// round 12
// speedup vs baseline: 1.0090x; 1.0090x over previous
#include <cuda_runtime.h>
#include <cuda_fp16.h>
#include <cstdint>

// FlashAttention B=2,H=16,N=4096,D=64 fp32. logits=(q.k)/64.
// HMMA mma.sync fp16 path (plain-sm_103 toolchain; fp8 ruled out: per-element
// quantization noise passes straight through to output rel_err).
// R11 = R8/R6 config (2 CTAs/SM, NBUF=4 mbarrier ring, f16x2 exp) with the
// S-GEMM SPLIT PER M-SLICE: slice0's scores finish after 32 MMAs so its
// softmax overlaps slice1's S-GEMM; per-slice K fragment reloads (+8 ldsm4).

namespace {
constexpr int BHn = 32;
constexpr int NSEQ = 4096;
constexpr int DH = 64;
constexpr int BM = 128;
constexpr int BN = 64;
constexpr int NKV = NSEQ / BN;  // 64
constexpr int NTH = 128;        // 4 warps
constexpr int LDS = 72;         // smem row stride (halves)
constexpr int NBUF = 4;
constexpr float QS2 = 1.4426950408889634f / 64.0f;  // log2(e)/64
constexpr size_t ELEMS = (size_t)BHn * NSEQ * DH;

__device__ __half g_kh[ELEMS];
__device__ __half g_vh[ELEMS];

// smem layout (halves): Q | buf0(K|V) | buf1 | buf2 | buf3
constexpr int OQ = 0;
constexpr int QH = BM * LDS;       // 9216 halves
constexpr int KVH = 2 * BN * LDS;  // 9216 halves per buffer
constexpr int SMEM_BYTES = (QH + NBUF * KVH) * 2;  // 92160 B

__device__ __forceinline__ uint32_t s2u(const void* p) {
  return (uint32_t)__cvta_generic_to_shared(p);
}
__device__ __forceinline__ void cpa16(uint32_t dst, const void* src) {
  asm volatile("cp.async.cg.shared.global [%0], [%1], 16;" :: "r"(dst), "l"(src));
}
__device__ __forceinline__ void mbar_init(uint32_t a, uint32_t c) {
  asm volatile("mbarrier.init.shared.b64 [%0], %1;" :: "r"(a), "r"(c) : "memory");
}
__device__ __forceinline__ void mbar_arrive(uint32_t a) {
  asm volatile("mbarrier.arrive.shared.b64 _, [%0];" :: "r"(a) : "memory");
}
__device__ __forceinline__ void cpa_arrive(uint32_t a) {
  asm volatile("cp.async.mbarrier.arrive.noinc.shared.b64 [%0];" :: "r"(a) : "memory");
}
__device__ __forceinline__ void mbar_wait(uint32_t a, uint32_t ph) {
  asm volatile(
      "{\n\t.reg .pred P;\n"
      "W%=:\n\t"
      "mbarrier.try_wait.parity.acquire.cta.shared::cta.b64 P, [%0], %1, 0x989680;\n\t"
      "@P bra D%=;\n\t"
      "bra W%=;\n"
      "D%=:\n\t}"
      :: "r"(a), "r"(ph) : "memory");
}
__device__ __forceinline__ void ldsm4(uint32_t* r, uint32_t a) {
  asm volatile("ldmatrix.sync.aligned.m8n8.x4.shared.b16 {%0,%1,%2,%3}, [%4];"
               : "=r"(r[0]), "=r"(r[1]), "=r"(r[2]), "=r"(r[3]) : "r"(a));
}
__device__ __forceinline__ void ldsm4t(uint32_t* r, uint32_t a) {
  asm volatile("ldmatrix.sync.aligned.m8n8.x4.trans.shared.b16 {%0,%1,%2,%3}, [%4];"
               : "=r"(r[0]), "=r"(r[1]), "=r"(r[2]), "=r"(r[3]) : "r"(a));
}
__device__ __forceinline__ void mma16816(float* c, const uint32_t* a, const uint32_t* b) {
  asm volatile(
      "mma.sync.aligned.m16n8k16.row.col.f32.f16.f16.f32 "
      "{%0,%1,%2,%3}, {%4,%5,%6,%7}, {%8,%9}, {%0,%1,%2,%3};"
      : "+f"(c[0]), "+f"(c[1]), "+f"(c[2]), "+f"(c[3])
      : "r"(a[0]), "r"(a[1]), "r"(a[2]), "r"(a[3]), "r"(b[0]), "r"(b[1]));
}
__device__ __forceinline__ uint32_t pack2(float x, float y) {
  __half2 h = __floats2half2_rn(x, y);
  return *reinterpret_cast<uint32_t*>(&h);
}
__device__ __forceinline__ uint32_t ex2h2(uint32_t x) {
  uint32_t y;
  asm("ex2.approx.f16x2 %0, %1;" : "=r"(y) : "r"(x));
  return y;
}
__device__ __forceinline__ __half2 u2h2(uint32_t x) {
  return *reinterpret_cast<__half2*>(&x);
}
}  // namespace

// -------- prep: K,V fp32 -> fp16 ---------------------------------------------
__global__ void prep_kernel(const float* __restrict__ k, const float* __restrict__ v) {
  size_t i = (size_t)blockIdx.x * blockDim.x + threadIdx.x;
  const float4 fk = reinterpret_cast<const float4*>(k)[i];
  const float4 fv = reinterpret_cast<const float4*>(v)[i];
  reinterpret_cast<uint2*>(g_kh)[i] = make_uint2(pack2(fk.x, fk.y), pack2(fk.z, fk.w));
  reinterpret_cast<uint2*>(g_vh)[i] = make_uint2(pack2(fv.x, fv.y), pack2(fv.z, fv.w));
}

// -------- main attention kernel ----------------------------------------------
__global__ __launch_bounds__(NTH, 2)
void fa_hmma_kernel(const float* __restrict__ qg, float* __restrict__ out) {
  extern __shared__ __half sm[];
  __shared__ uint64_t barsto[2 * NBUF];  // full[0..3], empty[0..3]
  const uint32_t sb = s2u(sm);
  const uint32_t bfull = s2u(&barsto[0]);
  const uint32_t bempty = s2u(&barsto[NBUF]);

  const int tid = threadIdx.x;
  const int lane = tid & 31, warp = tid >> 5;
  const int mi = lane >> 3;
  const int li = lane & 7;
  const int bh = blockIdx.y, mblk = blockIdx.x;

  const float* qsrc = qg + ((size_t)bh * NSEQ + (size_t)mblk * BM) * DH;
  const __half* ksrc = g_kh + (size_t)bh * NSEQ * DH;
  const __half* vsrc = g_vh + (size_t)bh * NSEQ * DH;

  if (tid == 0) {
#pragma unroll
    for (int i = 0; i < NBUF; i++) {
      mbar_init(bfull + 8 * i, NTH);
      mbar_init(bempty + 8 * i, NTH);
    }
  }
  __syncthreads();

  // ---- prologue: start KV tiles 0,1 (cp.async); convert Q meanwhile ----
#pragma unroll
  for (int t0 = 0; t0 < 2; t0++) {
    const __half* kt = ksrc + (size_t)t0 * BN * DH;
    const __half* vt = vsrc + (size_t)t0 * BN * DH;
    const int ob = QH + t0 * KVH;
#pragma unroll
    for (int i = 0; i < 4; i++) {
      int idx = i * NTH + tid;
      int r = idx >> 3, c = (idx & 7) << 3;
      cpa16(sb + (uint32_t)(ob + r * LDS + c) * 2, kt + r * DH + c);
      cpa16(sb + (uint32_t)(ob + BN * LDS + r * LDS + c) * 2, vt + r * DH + c);
    }
    cpa_arrive(bfull + 8 * t0);
  }
  // Q: fp32 LDG -> scale(log2 domain) -> fp16 STS
#pragma unroll
  for (int i = 0; i < 16; i++) {
    int idx = i * NTH + tid;
    int r = idx >> 4, c = (idx & 15) << 2;
    float4 f = *reinterpret_cast<const float4*>(qsrc + r * DH + c);
    *reinterpret_cast<uint2*>(&sm[OQ + r * LDS + c]) =
        make_uint2(pack2(f.x * QS2, f.y * QS2), pack2(f.z * QS2, f.w * QS2));
  }
  __syncthreads();  // Q visible

  // ---- Q A-fragments (warp-M = 32) ----
  uint32_t qa[2][4][4];
#pragma unroll
  for (int s = 0; s < 2; s++)
#pragma unroll
    for (int kt = 0; kt < 4; kt++) {
      int row = warp * 32 + s * 16 + (mi & 1) * 8 + li;
      int col = kt * 16 + (mi >> 1) * 8;
      ldsm4(qa[s][kt], s2u(&sm[OQ + row * LDS + col]));
    }

  float oacc[2][8][4];
#pragma unroll
  for (int s = 0; s < 2; s++)
#pragma unroll
    for (int i = 0; i < 8; i++)
#pragma unroll
      for (int j = 0; j < 4; j++) oacc[s][i][j] = 0.f;
  float lsum[2][2] = {{0.f, 0.f}, {0.f, 0.f}};

#pragma unroll 1
  for (int t = 0; t < NKV; t++) {
    const int buf = t & 3;
    const int kb = QH + buf * KVH;
    const int vb = kb + BN * LDS;

    mbar_wait(bfull + 8 * buf, (uint32_t)((t >> 2) & 1));

    // ---- prefetch tile t+2 (distance 2, slot freed two tiles ago) ----
    if (t + 2 < NKV) {
      const int pb = (t + 2) & 3;
      if (t >= 2) mbar_wait(bempty + 8 * pb, (uint32_t)(((t - 2) >> 2) & 1));
      const __half* kn = ksrc + (size_t)(t + 2) * BN * DH;
      const __half* vn = vsrc + (size_t)(t + 2) * BN * DH;
      const int ob = QH + pb * KVH;
#pragma unroll
      for (int i = 0; i < 4; i++) {
        int idx = i * NTH + tid;
        int r = idx >> 3, c = (idx & 7) << 3;
        cpa16(sb + (uint32_t)(ob + r * LDS + c) * 2, kn + r * DH + c);
        cpa16(sb + (uint32_t)(ob + BN * LDS + r * LDS + c) * 2, vn + r * DH + c);
      }
      cpa_arrive(bfull + 8 * pb);
    }

    // ---- per-slice: S(s) -> softmax(s) -> PV(s) ----
    // Slice s's scores are complete after its own 32 MMAs, so softmax(s=0)
    // overlaps S-GEMM(s=1); only one slice's sacc is live at a time.
#pragma unroll
    for (int s = 0; s < 2; s++) {
      float sacc[8][4];
#pragma unroll
      for (int i = 0; i < 8; i++)
#pragma unroll
        for (int j = 0; j < 4; j++) sacc[i][j] = 0.f;

#pragma unroll
      for (int kt = 0; kt < 4; kt++)
#pragma unroll
        for (int p = 0; p < 4; p++) {
          int row = p * 16 + (mi >> 1) * 8 + li;
          int col = kt * 16 + (mi & 1) * 8;
          uint32_t bf[4];
          ldsm4(bf, s2u(&sm[kb + row * LDS + col]));
          mma16816(sacc[2 * p], qa[s][kt], bf);
          mma16816(sacc[2 * p + 1], qa[s][kt], bf + 2);
        }

      __half2 a0 = __float2half2_rn(0.f), a1 = a0;
#pragma unroll
      for (int kt = 0; kt < 4; kt++) {
        uint32_t pa[4];
        pa[0] = ex2h2(pack2(sacc[2 * kt][0], sacc[2 * kt][1]));
        pa[1] = ex2h2(pack2(sacc[2 * kt][2], sacc[2 * kt][3]));
        pa[2] = ex2h2(pack2(sacc[2 * kt + 1][0], sacc[2 * kt + 1][1]));
        pa[3] = ex2h2(pack2(sacc[2 * kt + 1][2], sacc[2 * kt + 1][3]));
        a0 = __hadd2(a0, __hadd2(u2h2(pa[0]), u2h2(pa[2])));
        a1 = __hadd2(a1, __hadd2(u2h2(pa[1]), u2h2(pa[3])));
#pragma unroll
        for (int d = 0; d < 4; d++) {
          int row = kt * 16 + (mi & 1) * 8 + li;
          int col = (2 * d + (mi >> 1)) * 8;
          uint32_t bf[4];
          ldsm4t(bf, s2u(&sm[vb + row * LDS + col]));
          mma16816(oacc[s][2 * d], pa, bf);
          mma16816(oacc[s][2 * d + 1], pa, bf + 2);
        }
      }
      lsum[s][0] += __low2float(a0) + __high2float(a0);
      lsum[s][1] += __low2float(a1) + __high2float(a1);
    }

    mbar_arrive(bempty + 8 * buf);  // done reading buf
  }

  // ---- epilogue: O / max(l, eps) ----
#pragma unroll
  for (int s = 0; s < 2; s++)
#pragma unroll
    for (int h = 0; h < 2; h++) {
      float ls = lsum[s][h];
      ls += __shfl_xor_sync(0xffffffffu, ls, 1);
      ls += __shfl_xor_sync(0xffffffffu, ls, 2);
      float inv = 1.0f / fmaxf(ls, 1e-6f);
      int row = mblk * BM + warp * 32 + s * 16 + h * 8 + (lane >> 2);
      float* op = out + ((size_t)bh * NSEQ + row) * DH;
      int cb = (lane & 3) * 2;
#pragma unroll
      for (int nt = 0; nt < 8; nt++) {
        float2 f = make_float2(oacc[s][nt][2 * h] * inv, oacc[s][nt][2 * h + 1] * inv);
        *reinterpret_cast<float2*>(op + nt * 8 + cb) = f;
      }
    }
}

extern "C" void kernel_launch(void* const* d_in, const int* in_sizes, int n_in,
                              void* d_out, int out_size) {
  const float* q = (const float*)d_in[0];
  const float* k = (const float*)d_in[1];
  const float* v = (const float*)d_in[2];
  float* out = (float*)d_out;

  prep_kernel<<<(int)(ELEMS / 4 / 256), 256>>>(k, v);

  cudaFuncSetAttribute(fa_hmma_kernel, cudaFuncAttributeMaxDynamicSharedMemorySize,
                       SMEM_BYTES);
  dim3 grid(NSEQ / BM, BHn);
  fa_hmma_kernel<<<grid, NTH, SMEM_BYTES>>>(q, out);
}

// round 13
// speedup vs baseline: 1.0529x; 1.0436x over previous
#include <cuda_runtime.h>
#include <cuda_fp16.h>
#include <cstdint>

// FlashAttention B=2,H=16,N=4096,D=64 fp32. logits=(q.k)/64.
// HMMA mma.sync fp16 path (plain-sm_103 toolchain; tcgen05/fp8 ruled out).
// R12: BN=128 (32 KV tiles, halved per-tile barrier/loop overhead),
// NBUF=3 ring with dist-1 top-of-loop prefetch (1 tile slack), Q staging
// aliased into ring slot 2 to fit 2 CTAs/SM. Per-slice S->exp->PV.

namespace {
constexpr int BHn = 32;
constexpr int NSEQ = 4096;
constexpr int DH = 64;
constexpr int BM = 128;
constexpr int BN = 128;
constexpr int NKV = NSEQ / BN;  // 32
constexpr int NTH = 128;        // 4 warps
constexpr int LDS = 72;         // smem row stride (halves)
constexpr int NBUF = 3;
constexpr float QS2 = 1.4426950408889634f / 64.0f;  // log2(e)/64
constexpr size_t ELEMS = (size_t)BHn * NSEQ * DH;

__device__ __half g_kh[ELEMS];
__device__ __half g_vh[ELEMS];

// smem (halves): ring slot i at i*KVH (K then V). Q staging aliases slot 2.
constexpr int KVH = 2 * BN * LDS;  // 18432 halves per buffer
constexpr int OQ = 2 * KVH;        // Q staging = slot 2 (first written at t=2)
constexpr int SMEM_BYTES = NBUF * KVH * 2;  // 110592 B

__device__ __forceinline__ uint32_t s2u(const void* p) {
  return (uint32_t)__cvta_generic_to_shared(p);
}
__device__ __forceinline__ void cpa16(uint32_t dst, const void* src) {
  asm volatile("cp.async.cg.shared.global [%0], [%1], 16;" :: "r"(dst), "l"(src));
}
__device__ __forceinline__ void mbar_init(uint32_t a, uint32_t c) {
  asm volatile("mbarrier.init.shared.b64 [%0], %1;" :: "r"(a), "r"(c) : "memory");
}
__device__ __forceinline__ void mbar_arrive(uint32_t a) {
  asm volatile("mbarrier.arrive.shared.b64 _, [%0];" :: "r"(a) : "memory");
}
__device__ __forceinline__ void cpa_arrive(uint32_t a) {
  asm volatile("cp.async.mbarrier.arrive.noinc.shared.b64 [%0];" :: "r"(a) : "memory");
}
__device__ __forceinline__ void mbar_wait(uint32_t a, uint32_t ph) {
  asm volatile(
      "{\n\t.reg .pred P;\n"
      "W%=:\n\t"
      "mbarrier.try_wait.parity.acquire.cta.shared::cta.b64 P, [%0], %1, 0x989680;\n\t"
      "@P bra D%=;\n\t"
      "bra W%=;\n"
      "D%=:\n\t}"
      :: "r"(a), "r"(ph) : "memory");
}
__device__ __forceinline__ void ldsm4(uint32_t* r, uint32_t a) {
  asm volatile("ldmatrix.sync.aligned.m8n8.x4.shared.b16 {%0,%1,%2,%3}, [%4];"
               : "=r"(r[0]), "=r"(r[1]), "=r"(r[2]), "=r"(r[3]) : "r"(a));
}
__device__ __forceinline__ void ldsm4t(uint32_t* r, uint32_t a) {
  asm volatile("ldmatrix.sync.aligned.m8n8.x4.trans.shared.b16 {%0,%1,%2,%3}, [%4];"
               : "=r"(r[0]), "=r"(r[1]), "=r"(r[2]), "=r"(r[3]) : "r"(a));
}
__device__ __forceinline__ void mma16816(float* c, const uint32_t* a, const uint32_t* b) {
  asm volatile(
      "mma.sync.aligned.m16n8k16.row.col.f32.f16.f16.f32 "
      "{%0,%1,%2,%3}, {%4,%5,%6,%7}, {%8,%9}, {%0,%1,%2,%3};"
      : "+f"(c[0]), "+f"(c[1]), "+f"(c[2]), "+f"(c[3])
      : "r"(a[0]), "r"(a[1]), "r"(a[2]), "r"(a[3]), "r"(b[0]), "r"(b[1]));
}
__device__ __forceinline__ uint32_t pack2(float x, float y) {
  __half2 h = __floats2half2_rn(x, y);
  return *reinterpret_cast<uint32_t*>(&h);
}
__device__ __forceinline__ uint32_t ex2h2(uint32_t x) {
  uint32_t y;
  asm("ex2.approx.f16x2 %0, %1;" : "=r"(y) : "r"(x));
  return y;
}
__device__ __forceinline__ __half2 u2h2(uint32_t x) {
  return *reinterpret_cast<__half2*>(&x);
}
}  // namespace

// -------- prep: K,V fp32 -> fp16 ---------------------------------------------
__global__ void prep_kernel(const float* __restrict__ k, const float* __restrict__ v) {
  size_t i = (size_t)blockIdx.x * blockDim.x + threadIdx.x;
  const float4 fk = reinterpret_cast<const float4*>(k)[i];
  const float4 fv = reinterpret_cast<const float4*>(v)[i];
  reinterpret_cast<uint2*>(g_kh)[i] = make_uint2(pack2(fk.x, fk.y), pack2(fk.z, fk.w));
  reinterpret_cast<uint2*>(g_vh)[i] = make_uint2(pack2(fv.x, fv.y), pack2(fv.z, fv.w));
}

// -------- main attention kernel ----------------------------------------------
__global__ __launch_bounds__(NTH, 2)
void fa_hmma_kernel(const float* __restrict__ qg, float* __restrict__ out) {
  extern __shared__ __half sm[];
  __shared__ uint64_t barsto[2 * NBUF];  // full[0..2], empty[0..2]
  const uint32_t sb = s2u(sm);
  const uint32_t bfull = s2u(&barsto[0]);
  const uint32_t bempty = s2u(&barsto[NBUF]);

  const int tid = threadIdx.x;
  const int lane = tid & 31, warp = tid >> 5;
  const int mi = lane >> 3;
  const int li = lane & 7;
  const int bh = blockIdx.y, mblk = blockIdx.x;

  const float* qsrc = qg + ((size_t)bh * NSEQ + (size_t)mblk * BM) * DH;
  const __half* ksrc = g_kh + (size_t)bh * NSEQ * DH;
  const __half* vsrc = g_vh + (size_t)bh * NSEQ * DH;

  if (tid == 0) {
#pragma unroll
    for (int i = 0; i < NBUF; i++) {
      mbar_init(bfull + 8 * i, NTH);
      mbar_init(bempty + 8 * i, NTH);
    }
  }
  __syncthreads();

  // ---- prologue: start KV tile 0 into slot 0 (cp.async) ----
  {
#pragma unroll
    for (int i = 0; i < 8; i++) {  // K: 128 rows x 8 chunks; V same
      int idx = i * NTH + tid;
      int r = idx >> 3, c = (idx & 7) << 3;
      cpa16(sb + (uint32_t)(r * LDS + c) * 2, ksrc + r * DH + c);
      cpa16(sb + (uint32_t)(BN * LDS + r * LDS + c) * 2, vsrc + r * DH + c);
    }
    cpa_arrive(bfull + 0);
  }
  // Q: fp32 LDG -> scale(log2 domain) -> fp16 STS into slot-2 staging area
#pragma unroll
  for (int i = 0; i < 16; i++) {
    int idx = i * NTH + tid;
    int r = idx >> 4, c = (idx & 15) << 2;
    float4 f = *reinterpret_cast<const float4*>(qsrc + r * DH + c);
    *reinterpret_cast<uint2*>(&sm[OQ + r * LDS + c]) =
        make_uint2(pack2(f.x * QS2, f.y * QS2), pack2(f.z * QS2, f.w * QS2));
  }
  __syncthreads();  // Q visible

  // ---- Q A-fragments (warp-M = 32) ----
  uint32_t qa[2][4][4];
#pragma unroll
  for (int s = 0; s < 2; s++)
#pragma unroll
    for (int kt = 0; kt < 4; kt++) {
      int row = warp * 32 + s * 16 + (mi & 1) * 8 + li;
      int col = kt * 16 + (mi >> 1) * 8;
      ldsm4(qa[s][kt], s2u(&sm[OQ + row * LDS + col]));
    }
  __syncthreads();  // all warps done reading Q: slot 2 may be overwritten (t=1 prefetch)

  float oacc[2][8][4];
#pragma unroll
  for (int s = 0; s < 2; s++)
#pragma unroll
    for (int i = 0; i < 8; i++)
#pragma unroll
      for (int j = 0; j < 4; j++) oacc[s][i][j] = 0.f;
  float lsum[2][2] = {{0.f, 0.f}, {0.f, 0.f}};

#pragma unroll 1
  for (int t = 0; t < NKV; t++) {
    const int buf = t % 3;
    const int kb = buf * KVH;
    const int vb = kb + BN * LDS;

    // ---- prefetch tile t+1 (distance 1 at loop top: slack = 1 full tile) ----
    const int u = t + 1;
    if (u < NKV) {
      const int pb = u % 3;
      if (u >= 3) mbar_wait(bempty + 8 * pb, (uint32_t)(((u - 3) / 3) & 1));
      const __half* kn = ksrc + (size_t)u * BN * DH;
      const __half* vn = vsrc + (size_t)u * BN * DH;
      const int ob = pb * KVH;
#pragma unroll
      for (int i = 0; i < 8; i++) {
        int idx = i * NTH + tid;
        int r = idx >> 3, c = (idx & 7) << 3;
        cpa16(sb + (uint32_t)(ob + r * LDS + c) * 2, kn + r * DH + c);
        cpa16(sb + (uint32_t)(ob + BN * LDS + r * LDS + c) * 2, vn + r * DH + c);
      }
      cpa_arrive(bfull + 8 * pb);
    }

    mbar_wait(bfull + 8 * buf, (uint32_t)((t / 3) & 1));

    // ---- per-slice: S(s) -> exp -> PV(s); one slice's sacc live at a time ----
#pragma unroll
    for (int s = 0; s < 2; s++) {
      float sacc[16][4];
#pragma unroll
      for (int i = 0; i < 16; i++)
#pragma unroll
        for (int j = 0; j < 4; j++) sacc[i][j] = 0.f;

#pragma unroll
      for (int kt = 0; kt < 4; kt++)
#pragma unroll
        for (int p = 0; p < 8; p++) {
          int row = p * 16 + (mi >> 1) * 8 + li;
          int col = kt * 16 + (mi & 1) * 8;
          uint32_t bf[4];
          ldsm4(bf, s2u(&sm[kb + row * LDS + col]));
          mma16816(sacc[2 * p], qa[s][kt], bf);
          mma16816(sacc[2 * p + 1], qa[s][kt], bf + 2);
        }

      __half2 a0 = __float2half2_rn(0.f), a1 = a0;
#pragma unroll
      for (int g = 0; g < 8; g++) {
        uint32_t pa[4];
        pa[0] = ex2h2(pack2(sacc[2 * g][0], sacc[2 * g][1]));
        pa[1] = ex2h2(pack2(sacc[2 * g][2], sacc[2 * g][3]));
        pa[2] = ex2h2(pack2(sacc[2 * g + 1][0], sacc[2 * g + 1][1]));
        pa[3] = ex2h2(pack2(sacc[2 * g + 1][2], sacc[2 * g + 1][3]));
        a0 = __hadd2(a0, __hadd2(u2h2(pa[0]), u2h2(pa[2])));
        a1 = __hadd2(a1, __hadd2(u2h2(pa[1]), u2h2(pa[3])));
#pragma unroll
        for (int d = 0; d < 4; d++) {
          int row = g * 16 + (mi & 1) * 8 + li;
          int col = (2 * d + (mi >> 1)) * 8;
          uint32_t bf[4];
          ldsm4t(bf, s2u(&sm[vb + row * LDS + col]));
          mma16816(oacc[s][2 * d], pa, bf);
          mma16816(oacc[s][2 * d + 1], pa, bf + 2);
        }
      }
      lsum[s][0] += __low2float(a0) + __high2float(a0);
      lsum[s][1] += __low2float(a1) + __high2float(a1);
    }

    mbar_arrive(bempty + 8 * buf);  // done reading buf
  }

  // ---- epilogue: O / max(l, eps) ----
#pragma unroll
  for (int s = 0; s < 2; s++)
#pragma unroll
    for (int h = 0; h < 2; h++) {
      float ls = lsum[s][h];
      ls += __shfl_xor_sync(0xffffffffu, ls, 1);
      ls += __shfl_xor_sync(0xffffffffu, ls, 2);
      float inv = 1.0f / fmaxf(ls, 1e-6f);
      int row = mblk * BM + warp * 32 + s * 16 + h * 8 + (lane >> 2);
      float* op = out + ((size_t)bh * NSEQ + row) * DH;
      int cb = (lane & 3) * 2;
#pragma unroll
      for (int nt = 0; nt < 8; nt++) {
        float2 f = make_float2(oacc[s][nt][2 * h] * inv, oacc[s][nt][2 * h + 1] * inv);
        *reinterpret_cast<float2*>(op + nt * 8 + cb) = f;
      }
    }
}

extern "C" void kernel_launch(void* const* d_in, const int* in_sizes, int n_in,
                              void* d_out, int out_size) {
  const float* q = (const float*)d_in[0];
  const float* k = (const float*)d_in[1];
  const float* v = (const float*)d_in[2];
  float* out = (float*)d_out;

  prep_kernel<<<(int)(ELEMS / 4 / 256), 256>>>(k, v);

  cudaFuncSetAttribute(fa_hmma_kernel, cudaFuncAttributeMaxDynamicSharedMemorySize,
                       SMEM_BYTES);
  dim3 grid(NSEQ / BM, BHn);
  fa_hmma_kernel<<<grid, NTH, SMEM_BYTES>>>(q, out);
}

// round 14
// speedup vs baseline: 1.0598x; 1.0065x over previous
#include <cuda_runtime.h>
#include <cuda_fp16.h>
#include <cstdint>

// FlashAttention B=2,H=16,N=4096,D=64 fp32. logits=(q.k)/64.
// HMMA mma.sync fp16 path (plain-sm_103 toolchain; tcgen05/fp8 ruled out).
// R13 = R12 (BN=128, NBUF=3 ring, dist-1 prefetch, Q aliased in slot 2)
// + cross-CTA phase stagger: the 2nd CTA arriving on each SM spins ~1200cyc
// once, so its MUFU softmax phases interleave with its partner's HMMA phases.

namespace {
constexpr int BHn = 32;
constexpr int NSEQ = 4096;
constexpr int DH = 64;
constexpr int BM = 128;
constexpr int BN = 128;
constexpr int NKV = NSEQ / BN;  // 32
constexpr int NTH = 128;        // 4 warps
constexpr int LDS = 72;         // smem row stride (halves)
constexpr int NBUF = 3;
constexpr float QS2 = 1.4426950408889634f / 64.0f;  // log2(e)/64
constexpr size_t ELEMS = (size_t)BHn * NSEQ * DH;

__device__ __half g_kh[ELEMS];
__device__ __half g_vh[ELEMS];
__device__ unsigned int g_smctr[256];  // per-SM arrival counters (monotonic)

// smem (halves): ring slot i at i*KVH (K then V). Q staging aliases slot 2.
constexpr int KVH = 2 * BN * LDS;  // 18432 halves per buffer
constexpr int OQ = 2 * KVH;        // Q staging = slot 2 (first written at t=2)
constexpr int SMEM_BYTES = NBUF * KVH * 2;  // 110592 B

__device__ __forceinline__ uint32_t s2u(const void* p) {
  return (uint32_t)__cvta_generic_to_shared(p);
}
__device__ __forceinline__ void cpa16(uint32_t dst, const void* src) {
  asm volatile("cp.async.cg.shared.global [%0], [%1], 16;" :: "r"(dst), "l"(src));
}
__device__ __forceinline__ void mbar_init(uint32_t a, uint32_t c) {
  asm volatile("mbarrier.init.shared.b64 [%0], %1;" :: "r"(a), "r"(c) : "memory");
}
__device__ __forceinline__ void mbar_arrive(uint32_t a) {
  asm volatile("mbarrier.arrive.shared.b64 _, [%0];" :: "r"(a) : "memory");
}
__device__ __forceinline__ void cpa_arrive(uint32_t a) {
  asm volatile("cp.async.mbarrier.arrive.noinc.shared.b64 [%0];" :: "r"(a) : "memory");
}
__device__ __forceinline__ void mbar_wait(uint32_t a, uint32_t ph) {
  asm volatile(
      "{\n\t.reg .pred P;\n"
      "W%=:\n\t"
      "mbarrier.try_wait.parity.acquire.cta.shared::cta.b64 P, [%0], %1, 0x989680;\n\t"
      "@P bra D%=;\n\t"
      "bra W%=;\n"
      "D%=:\n\t}"
      :: "r"(a), "r"(ph) : "memory");
}
__device__ __forceinline__ void ldsm4(uint32_t* r, uint32_t a) {
  asm volatile("ldmatrix.sync.aligned.m8n8.x4.shared.b16 {%0,%1,%2,%3}, [%4];"
               : "=r"(r[0]), "=r"(r[1]), "=r"(r[2]), "=r"(r[3]) : "r"(a));
}
__device__ __forceinline__ void ldsm4t(uint32_t* r, uint32_t a) {
  asm volatile("ldmatrix.sync.aligned.m8n8.x4.trans.shared.b16 {%0,%1,%2,%3}, [%4];"
               : "=r"(r[0]), "=r"(r[1]), "=r"(r[2]), "=r"(r[3]) : "r"(a));
}
__device__ __forceinline__ void mma16816(float* c, const uint32_t* a, const uint32_t* b) {
  asm volatile(
      "mma.sync.aligned.m16n8k16.row.col.f32.f16.f16.f32 "
      "{%0,%1,%2,%3}, {%4,%5,%6,%7}, {%8,%9}, {%0,%1,%2,%3};"
      : "+f"(c[0]), "+f"(c[1]), "+f"(c[2]), "+f"(c[3])
      : "r"(a[0]), "r"(a[1]), "r"(a[2]), "r"(a[3]), "r"(b[0]), "r"(b[1]));
}
__device__ __forceinline__ uint32_t pack2(float x, float y) {
  __half2 h = __floats2half2_rn(x, y);
  return *reinterpret_cast<uint32_t*>(&h);
}
__device__ __forceinline__ uint32_t ex2h2(uint32_t x) {
  uint32_t y;
  asm("ex2.approx.f16x2 %0, %1;" : "=r"(y) : "r"(x));
  return y;
}
__device__ __forceinline__ __half2 u2h2(uint32_t x) {
  return *reinterpret_cast<__half2*>(&x);
}
}  // namespace

// -------- prep: K,V fp32 -> fp16 ---------------------------------------------
__global__ void prep_kernel(const float* __restrict__ k, const float* __restrict__ v) {
  size_t i = (size_t)blockIdx.x * blockDim.x + threadIdx.x;
  const float4 fk = reinterpret_cast<const float4*>(k)[i];
  const float4 fv = reinterpret_cast<const float4*>(v)[i];
  reinterpret_cast<uint2*>(g_kh)[i] = make_uint2(pack2(fk.x, fk.y), pack2(fk.z, fk.w));
  reinterpret_cast<uint2*>(g_vh)[i] = make_uint2(pack2(fv.x, fv.y), pack2(fv.z, fv.w));
}

// -------- main attention kernel ----------------------------------------------
__global__ __launch_bounds__(NTH, 2)
void fa_hmma_kernel(const float* __restrict__ qg, float* __restrict__ out) {
  extern __shared__ __half sm[];
  __shared__ uint64_t barsto[2 * NBUF];  // full[0..2], empty[0..2]
  __shared__ int srank;
  const uint32_t sb = s2u(sm);
  const uint32_t bfull = s2u(&barsto[0]);
  const uint32_t bempty = s2u(&barsto[NBUF]);

  const int tid = threadIdx.x;
  const int lane = tid & 31, warp = tid >> 5;
  const int mi = lane >> 3;
  const int li = lane & 7;
  const int bh = blockIdx.y, mblk = blockIdx.x;

  const float* qsrc = qg + ((size_t)bh * NSEQ + (size_t)mblk * BM) * DH;
  const __half* ksrc = g_kh + (size_t)bh * NSEQ * DH;
  const __half* vsrc = g_vh + (size_t)bh * NSEQ * DH;

  if (tid == 0) {
#pragma unroll
    for (int i = 0; i < NBUF; i++) {
      mbar_init(bfull + 8 * i, NTH);
      mbar_init(bempty + 8 * i, NTH);
    }
    uint32_t smid;
    asm("mov.u32 %0, %%smid;" : "=r"(smid));
    srank = (int)(atomicAdd(&g_smctr[smid & 255], 1u) & 1u);
  }
  __syncthreads();

  // ---- prologue: start KV tile 0 into slot 0 (cp.async) ----
  {
#pragma unroll
    for (int i = 0; i < 8; i++) {  // K: 128 rows x 8 chunks; V same
      int idx = i * NTH + tid;
      int r = idx >> 3, c = (idx & 7) << 3;
      cpa16(sb + (uint32_t)(r * LDS + c) * 2, ksrc + r * DH + c);
      cpa16(sb + (uint32_t)(BN * LDS + r * LDS + c) * 2, vsrc + r * DH + c);
    }
    cpa_arrive(bfull + 0);
  }
  // Q: fp32 LDG -> scale(log2 domain) -> fp16 STS into slot-2 staging area
#pragma unroll
  for (int i = 0; i < 16; i++) {
    int idx = i * NTH + tid;
    int r = idx >> 4, c = (idx & 15) << 2;
    float4 f = *reinterpret_cast<const float4*>(qsrc + r * DH + c);
    *reinterpret_cast<uint2*>(&sm[OQ + r * LDS + c]) =
        make_uint2(pack2(f.x * QS2, f.y * QS2), pack2(f.z * QS2, f.w * QS2));
  }
  __syncthreads();  // Q visible

  // ---- Q A-fragments (warp-M = 32) ----
  uint32_t qa[2][4][4];
#pragma unroll
  for (int s = 0; s < 2; s++)
#pragma unroll
    for (int kt = 0; kt < 4; kt++) {
      int row = warp * 32 + s * 16 + (mi & 1) * 8 + li;
      int col = kt * 16 + (mi >> 1) * 8;
      ldsm4(qa[s][kt], s2u(&sm[OQ + row * LDS + col]));
    }
  __syncthreads();  // all warps done reading Q: slot 2 may be overwritten (t=1 prefetch)

  // ---- cross-CTA phase stagger: 2nd CTA on this SM spins ~1200 cyc once ----
  if (srank) {
    uint32_t t0 = (uint32_t)clock();
    while ((uint32_t)clock() - t0 < 1200u) {}
  }

  float oacc[2][8][4];
#pragma unroll
  for (int s = 0; s < 2; s++)
#pragma unroll
    for (int i = 0; i < 8; i++)
#pragma unroll
      for (int j = 0; j < 4; j++) oacc[s][i][j] = 0.f;
  float lsum[2][2] = {{0.f, 0.f}, {0.f, 0.f}};

#pragma unroll 1
  for (int t = 0; t < NKV; t++) {
    const int buf = t % 3;
    const int kb = buf * KVH;
    const int vb = kb + BN * LDS;

    // ---- prefetch tile t+1 (distance 1 at loop top: slack = 1 full tile) ----
    const int u = t + 1;
    if (u < NKV) {
      const int pb = u % 3;
      if (u >= 3) mbar_wait(bempty + 8 * pb, (uint32_t)(((u - 3) / 3) & 1));
      const __half* kn = ksrc + (size_t)u * BN * DH;
      const __half* vn = vsrc + (size_t)u * BN * DH;
      const int ob = pb * KVH;
#pragma unroll
      for (int i = 0; i < 8; i++) {
        int idx = i * NTH + tid;
        int r = idx >> 3, c = (idx & 7) << 3;
        cpa16(sb + (uint32_t)(ob + r * LDS + c) * 2, kn + r * DH + c);
        cpa16(sb + (uint32_t)(ob + BN * LDS + r * LDS + c) * 2, vn + r * DH + c);
      }
      cpa_arrive(bfull + 8 * pb);
    }

    mbar_wait(bfull + 8 * buf, (uint32_t)((t / 3) & 1));

    // ---- per-slice: S(s) -> exp -> PV(s); one slice's sacc live at a time ----
#pragma unroll
    for (int s = 0; s < 2; s++) {
      float sacc[16][4];
#pragma unroll
      for (int i = 0; i < 16; i++)
#pragma unroll
        for (int j = 0; j < 4; j++) sacc[i][j] = 0.f;

#pragma unroll
      for (int kt = 0; kt < 4; kt++)
#pragma unroll
        for (int p = 0; p < 8; p++) {
          int row = p * 16 + (mi >> 1) * 8 + li;
          int col = kt * 16 + (mi & 1) * 8;
          uint32_t bf[4];
          ldsm4(bf, s2u(&sm[kb + row * LDS + col]));
          mma16816(sacc[2 * p], qa[s][kt], bf);
          mma16816(sacc[2 * p + 1], qa[s][kt], bf + 2);
        }

      __half2 a0 = __float2half2_rn(0.f), a1 = a0;
#pragma unroll
      for (int g = 0; g < 8; g++) {
        uint32_t pa[4];
        pa[0] = ex2h2(pack2(sacc[2 * g][0], sacc[2 * g][1]));
        pa[1] = ex2h2(pack2(sacc[2 * g][2], sacc[2 * g][3]));
        pa[2] = ex2h2(pack2(sacc[2 * g + 1][0], sacc[2 * g + 1][1]));
        pa[3] = ex2h2(pack2(sacc[2 * g + 1][2], sacc[2 * g + 1][3]));
        a0 = __hadd2(a0, __hadd2(u2h2(pa[0]), u2h2(pa[2])));
        a1 = __hadd2(a1, __hadd2(u2h2(pa[1]), u2h2(pa[3])));
#pragma unroll
        for (int d = 0; d < 4; d++) {
          int row = g * 16 + (mi & 1) * 8 + li;
          int col = (2 * d + (mi >> 1)) * 8;
          uint32_t bf[4];
          ldsm4t(bf, s2u(&sm[vb + row * LDS + col]));
          mma16816(oacc[s][2 * d], pa, bf);
          mma16816(oacc[s][2 * d + 1], pa, bf + 2);
        }
      }
      lsum[s][0] += __low2float(a0) + __high2float(a0);
      lsum[s][1] += __low2float(a1) + __high2float(a1);
    }

    mbar_arrive(bempty + 8 * buf);  // done reading buf
  }

  // ---- epilogue: O / max(l, eps) ----
#pragma unroll
  for (int s = 0; s < 2; s++)
#pragma unroll
    for (int h = 0; h < 2; h++) {
      float ls = lsum[s][h];
      ls += __shfl_xor_sync(0xffffffffu, ls, 1);
      ls += __shfl_xor_sync(0xffffffffu, ls, 2);
      float inv = 1.0f / fmaxf(ls, 1e-6f);
      int row = mblk * BM + warp * 32 + s * 16 + h * 8 + (lane >> 2);
      float* op = out + ((size_t)bh * NSEQ + row) * DH;
      int cb = (lane & 3) * 2;
#pragma unroll
      for (int nt = 0; nt < 8; nt++) {
        float2 f = make_float2(oacc[s][nt][2 * h] * inv, oacc[s][nt][2 * h + 1] * inv);
        *reinterpret_cast<float2*>(op + nt * 8 + cb) = f;
      }
    }
}

extern "C" void kernel_launch(void* const* d_in, const int* in_sizes, int n_in,
                              void* d_out, int out_size) {
  const float* q = (const float*)d_in[0];
  const float* k = (const float*)d_in[1];
  const float* v = (const float*)d_in[2];
  float* out = (float*)d_out;

  prep_kernel<<<(int)(ELEMS / 4 / 256), 256>>>(k, v);

  cudaFuncSetAttribute(fa_hmma_kernel, cudaFuncAttributeMaxDynamicSharedMemorySize,
                       SMEM_BYTES);
  dim3 grid(NSEQ / BM, BHn);
  fa_hmma_kernel<<<grid, NTH, SMEM_BYTES>>>(q, out);
}